// round 3
// baseline (speedup 1.0000x reference)
#include <cuda_runtime.h>

#define NSTR   4
#define T_LEN  8192
#define D_HID  2048
#define ND     8192
#define NOUT   24
#define NACC   25
#define NPACK  12                // 12 packed output-pair accumulators (+1 sumsq)
#define KQ     4                 // K-split per segment
#define KCHUNK (D_HID / KQ)      // 512
#define KC     64                // K rows per staged tile
#define NTILES (KCHUNK / KC)     // 8

// interleaved weights: [w*2048+k][j]  (j = output 0..23)
__device__ __align__(16) float g_wint[NSTR * D_HID * NOUT];     // 768 KB
// partials: [kq][acc][row]
__device__ float g_scratch[KQ][NACC][T_LEN];                    // 3.2 MB

typedef unsigned long long ull;

__device__ __forceinline__ void fma2(ull &acc, ull a, ull b) {
    asm("fma.rn.f32x2 %0, %1, %2, %0;" : "+l"(acc) : "l"(a), "l"(b));
}
__device__ __forceinline__ ull dup2(float x) {
    ull r; asm("mov.b64 %0, {%1, %1};" : "=l"(r) : "f"(x)); return r;
}
__device__ __forceinline__ ull pack2(float a, float b) {
    ull r; asm("mov.b64 %0, {%1, %2};" : "=l"(r) : "f"(a), "f"(b)); return r;
}
__device__ __forceinline__ float lo32(ull v) {
    return __uint_as_float((unsigned)(v & 0xffffffffull));
}
__device__ __forceinline__ float hi32(ull v) {
    return __uint_as_float((unsigned)(v >> 32));
}
__device__ __forceinline__ void cp16(unsigned dst, const float* src) {
    asm volatile("cp.async.cg.shared.global [%0], [%1], 16;\n"
                 :: "r"(dst), "l"(src) : "memory");
}
__device__ __forceinline__ void cp_commit() {
    asm volatile("cp.async.commit_group;\n" ::: "memory");
}
template <int N>
__device__ __forceinline__ void cp_wait() {
    asm volatile("cp.async.wait_group %0;\n" :: "n"(N) : "memory");
}

// ---- weight interleave: g_wint[(w*2048+k)*24 + j] = W_j[w*2048+k] ----
__global__ void mhc_prep(const float* __restrict__ Wpre,
                         const float* __restrict__ Wpost,
                         const float* __restrict__ Wres)
{
    const int j   = blockIdx.y;                      // 0..23
    const int idx = blockIdx.x * 256 + threadIdx.x;  // 0..8191 over (w,k)
    const float* src;
    if (j < 4)      src = Wpre  + (size_t)j * ND;
    else if (j < 8) src = Wpost + (size_t)(j - 4) * ND;
    else            src = Wres  + (size_t)(j - 8) * ND;
    g_wint[(size_t)idx * NOUT + j] = src[idx];
}

__global__ __launch_bounds__(128, 4)
void mhc_part(const float* __restrict__ stream)
{
    // per-warp double-buffered tiles: KC rows x 24 floats (96B rows)
    __shared__ __align__(16) float ws[4][2][KC * NOUT];   // 49,152 B

    const int lane   = threadIdx.x & 31;
    const int w      = threadIdx.x >> 5;
    const int rowblk = blockIdx.x & 255;
    const int kq     = blockIdx.x >> 8;
    const int t      = rowblk * 32 + lane;

    const float* xrow = stream + ((size_t)w * T_LEN + t) * D_HID + kq * KCHUNK;
    const float* wsrc = g_wint + ((size_t)w * D_HID + (size_t)kq * KCHUNK) * NOUT;

    const unsigned ws_u32 = (unsigned)__cvta_generic_to_shared(&ws[w][0][0]);

    // one tile = 64 k-rows x 96B = 6144B = 384 16B chunks, identical layout
    auto stage = [&](int tile, int b) {
        const float*  src   = wsrc + (size_t)tile * KC * NOUT;
        const unsigned dbase = ws_u32 + (unsigned)(b * KC * NOUT) * 4u;
#pragma unroll
        for (int i = 0; i < 12; i++) {
            const int c = lane + 32 * i;
            cp16(dbase + (unsigned)c * 16u, src + c * 4);
        }
        cp_commit();
    };

    ull acc[NPACK];
#pragma unroll
    for (int i = 0; i < NPACK; i++) acc[i] = 0ull;
    ull accss = 0ull;

    stage(0, 0);
    int buf = 0;

    for (int tile = 0; tile < NTILES; ++tile) {
        if (tile + 1 < NTILES) { stage(tile + 1, buf ^ 1); cp_wait<1>(); }
        else                   { cp_wait<0>(); }
        __syncwarp();

        const float4* xp = reinterpret_cast<const float4*>(xrow + tile * KC);
        const float*  wb = &ws[w][buf][0];

#pragma unroll 4
        for (int p = 0; p < KC / 4; ++p) {
            const float4 xq = xp[p];
            const float* wk = wb + p * 4 * NOUT;

#pragma unroll
            for (int s = 0; s < 4; ++s) {
                const float x = (s == 0) ? xq.x : (s == 1) ? xq.y
                              : (s == 2) ? xq.z : xq.w;
                const ull xx = dup2(x);
                const ulonglong2* wr =
                    reinterpret_cast<const ulonglong2*>(wk + s * NOUT);
#pragma unroll
                for (int m = 0; m < 6; ++m) {
                    const ulonglong2 wv = wr[m];     // LDS.128 broadcast
                    fma2(acc[2 * m],     xx, wv.x);  // outputs 4m, 4m+1
                    fma2(acc[2 * m + 1], xx, wv.y);  // outputs 4m+2, 4m+3
                }
            }
            const ull x01 = pack2(xq.x, xq.y);
            const ull x23 = pack2(xq.z, xq.w);
            fma2(accss, x01, x01);
            fma2(accss, x23, x23);
        }
        __syncwarp();
        buf ^= 1;
    }

    // unpack: acc[m] lo = output 2m, hi = output 2m+1
    float resv[NACC];
#pragma unroll
    for (int m = 0; m < NPACK; m++) {
        resv[2 * m]     = lo32(acc[m]);
        resv[2 * m + 1] = hi32(acc[m]);
    }
    resv[24] = lo32(accss) + hi32(accss);

    // cross-warp reduction through this warp's own smem region
    float* redw = &ws[w][0][0];          // 32*26 = 832 <= 1536 floats
    __syncwarp();
#pragma unroll
    for (int i = 0; i < NACC; i++) redw[lane * 26 + i] = resv[i];
    __syncthreads();

    if (w == 0) {
#pragma unroll
        for (int i = 0; i < NACC; i++) {
            const float v = ws[0][0][lane * 26 + i] + ws[1][0][lane * 26 + i]
                          + ws[2][0][lane * 26 + i] + ws[3][0][lane * 26 + i];
            g_scratch[kq][i][t] = v;
        }
    }
}

__global__ __launch_bounds__(256)
void mhc_epilogue(const float* __restrict__ bpre,
                  const float* __restrict__ bpost,
                  const float* __restrict__ bres,
                  const float* __restrict__ apre_p,
                  const float* __restrict__ apost_p,
                  const float* __restrict__ ares_p,
                  float* __restrict__ out)
{
    const int t = blockIdx.x * 256 + threadIdx.x;

    float v[NACC];
#pragma unroll
    for (int i = 0; i < NACC; i++)
        v[i] = g_scratch[0][i][t] + g_scratch[1][i][t]
             + g_scratch[2][i][t] + g_scratch[3][i][t];

    const float rn = rsqrtf(v[24] * (1.0f / (float)ND) + 1e-8f);

    const float apre  = *apre_p;
    const float apost = *apost_p;
    const float ares  = *ares_p;

    float* outres  = out;                          // (T,4,4)
    float* outpre  = out + (size_t)T_LEN * 16;     // (T,4)
    float* outpost = out + (size_t)T_LEN * 20;     // (T,4)

#pragma unroll
    for (int k = 0; k < 4; k++) {
        const float z = apre * v[k] * rn + bpre[k];
        outpre[(size_t)t * 4 + k] = 1.0f / (1.0f + expf(-z));
    }
#pragma unroll
    for (int k = 0; k < 4; k++) {
        const float z = apost * v[4 + k] * rn + bpost[k];
        outpost[(size_t)t * 4 + k] = 2.0f / (1.0f + expf(-z));
    }

    float M[16];
#pragma unroll
    for (int i = 0; i < 16; i++)
        M[i] = expf(ares * v[8 + i] * rn + bres[i]);

    for (int it = 0; it < 20; it++) {
#pragma unroll
        for (int a = 0; a < 4; a++) {
            const float r = 1.0f / (M[4*a] + M[4*a+1] + M[4*a+2] + M[4*a+3]);
            M[4*a] *= r; M[4*a+1] *= r; M[4*a+2] *= r; M[4*a+3] *= r;
        }
#pragma unroll
        for (int b = 0; b < 4; b++) {
            const float r = 1.0f / (M[b] + M[4+b] + M[8+b] + M[12+b]);
            M[b] *= r; M[4+b] *= r; M[8+b] *= r; M[12+b] *= r;
        }
    }
#pragma unroll
    for (int i = 0; i < 16; i++) outres[(size_t)t * 16 + i] = M[i];
}

extern "C" void kernel_launch(void* const* d_in, const int* in_sizes, int n_in,
                              void* d_out, int out_size) {
    const float* stream = (const float*)d_in[0];
    const float* Wpre   = (const float*)d_in[1];
    const float* Wpost  = (const float*)d_in[2];
    const float* Wres   = (const float*)d_in[3];
    const float* bpre   = (const float*)d_in[4];
    const float* bpost  = (const float*)d_in[5];
    const float* bres   = (const float*)d_in[6];
    const float* apre   = (const float*)d_in[7];
    const float* apost  = (const float*)d_in[8];
    const float* ares   = (const float*)d_in[9];

    dim3 pgrid(32, 24);
    mhc_prep<<<pgrid, 256>>>(Wpre, Wpost, Wres);
    mhc_part<<<256 * KQ, 128>>>(stream);
    mhc_epilogue<<<T_LEN / 256, 256>>>(bpre, bpost, bres, apre, apost, ares,
                                       (float*)d_out);
}